// round 4
// baseline (speedup 1.0000x reference)
#include <cuda_runtime.h>
#include <cuda_bf16.h>
#include <math.h>

#define L     8
#define NH    16
#define DH    64
#define SMAX  2048
#define H     1024
#define FFN   4096
#define ENC   1500
#define VOCAB 8192
#define FCH   48   // enc f-rows per k_wsum chunk (32*48 >= 1500)
#define CH    32   // attention key chunks

// ---------------- device state ----------------
__device__ __align__(16) float g_x[H];
__device__ __align__(16) float g_qkv[3 * H];      // q | k1 | v1
__device__ __align__(16) float g_ao[H];           // self-attn output
__device__ __align__(16) float g_qc[H];           // cross query
__device__ __align__(16) float g_U[NH * H];       // U[h][i] (transposed)
__device__ __align__(16) float g_sc[NH * ENC];    // cross scores -> attc (in place)
__device__ __align__(16) float g_W[NH * H];       // W[h][i] = sum_f attc[h,f]*enc[f,i]
__device__ __align__(16) float g_outc[H];         // cross-attn output
__device__ __align__(16) float g_ffn[FFN];
__device__ __align__(16) float g_logits[VOCAB];
__device__ float g_pm[NH * CH];
__device__ float g_ps[NH * CH];
__device__ __align__(16) float g_po[NH * CH * DH];
__device__ int   g_step_fallback[1] = {512};

// ---------------- block reductions ----------------
__device__ __forceinline__ float br_sum(float v, float* sb) {
    int tid = threadIdx.x, lane = tid & 31, w = tid >> 5;
#pragma unroll
    for (int o = 16; o; o >>= 1) v += __shfl_down_sync(0xffffffffu, v, o);
    if (lane == 0) sb[w] = v;
    __syncthreads();
    if (tid < 32) {
        int nw = (blockDim.x + 31) >> 5;
        float x = (tid < nw) ? sb[tid] : 0.0f;
#pragma unroll
        for (int o = 16; o; o >>= 1) x += __shfl_down_sync(0xffffffffu, x, o);
        if (tid == 0) sb[0] = x;
    }
    __syncthreads();
    float r = sb[0];
    __syncthreads();
    return r;
}

__device__ __forceinline__ float br_max(float v, float* sb) {
    int tid = threadIdx.x, lane = tid & 31, w = tid >> 5;
#pragma unroll
    for (int o = 16; o; o >>= 1) v = fmaxf(v, __shfl_down_sync(0xffffffffu, v, o));
    if (lane == 0) sb[w] = v;
    __syncthreads();
    if (tid < 32) {
        int nw = (blockDim.x + 31) >> 5;
        float x = (tid < nw) ? sb[tid] : -1e30f;
#pragma unroll
        for (int o = 16; o; o >>= 1) x = fmaxf(x, __shfl_down_sync(0xffffffffu, x, o));
        if (tid == 0) sb[0] = x;
    }
    __syncthreads();
    float r = sb[0];
    __syncthreads();
    return r;
}

__device__ __forceinline__ void ln_stats(float* sb, float& mean, float& rstd) {
    int tid = threadIdx.x;
    float s = 0.f;
    for (int i = tid; i < H; i += blockDim.x) s += g_x[i];
    mean = br_sum(s, sb) * (1.0f / H);
    float v = 0.f;
    for (int i = tid; i < H; i += blockDim.x) { float d = g_x[i] - mean; v += d * d; }
    rstd = rsqrtf(br_sum(v, sb) * (1.0f / H) + 1e-5f);
}

// ---------------- kernels ----------------

__global__ void k_copy(const float4* __restrict__ ck, const float4* __restrict__ cv,
                       float4* __restrict__ nk, float4* __restrict__ nv,
                       const int* __restrict__ stepp) {
    int step = stepp[0];
    size_t idx = (size_t)blockIdx.x * blockDim.x + threadIdx.x;
    const size_t half = (size_t)L * NH * SMAX * 16;
    if (idx >= 2 * half) return;
    const float4* src; float4* dst; size_t pos;
    if (idx < half) { src = ck; dst = nk; pos = idx; }
    else            { src = cv; dst = nv; pos = idx - half; }
    int t = (int)((pos >> 4) & (SMAX - 1));
    if (t < step)      dst[pos] = src[pos];
    else if (t > step) dst[pos] = make_float4(0.f, 0.f, 0.f, 0.f);
}

__global__ void k_init(const int* __restrict__ idp, const int* __restrict__ stepp,
                       const float* __restrict__ tok, const float* __restrict__ pos) {
    int tid = threadIdx.x;  // 1024
    int id = idp[0], st = stepp[0];
    g_x[tid] = tok[(size_t)id * H + tid] + pos[(size_t)st * H + tid];
    for (int i = tid; i < 3 * H; i += 1024) g_qkv[i] = 0.f;
}

// QKV: grid (3, 64), block 256, 16 rows/block, float4 cols
__global__ void k_gemv3_ln(const float* __restrict__ Wq, const float* __restrict__ Wk,
                           const float* __restrict__ Wv,
                           const float* __restrict__ g, const float* __restrict__ b) {
    __shared__ float sb[32];
    __shared__ float ac[16];
    int tid = threadIdx.x;
    float mean, rstd;
    ln_stats(sb, mean, rstd);
    int i0 = blockIdx.y * 16;
    if (tid < 16) { int i = i0 + tid; ac[tid] = (g_x[i] - mean) * rstd * g[i] + b[i]; }
    __syncthreads();
    const float* Wm = (blockIdx.x == 0) ? Wq : ((blockIdx.x == 1) ? Wk : Wv);
    int c0 = tid * 4;
    float4 acc = make_float4(0.f, 0.f, 0.f, 0.f);
#pragma unroll 4
    for (int r = 0; r < 16; r++) {
        float4 w = *(const float4*)(Wm + (size_t)(i0 + r) * H + c0);
        float a = ac[r];
        acc.x += a * w.x; acc.y += a * w.y; acc.z += a * w.z; acc.w += a * w.w;
    }
    float* o = &g_qkv[blockIdx.x * H + c0];
    atomicAdd(o, acc.x); atomicAdd(o + 1, acc.y);
    atomicAdd(o + 2, acc.z); atomicAdd(o + 3, acc.w);
}

// generic vectorized split-K GEMV. mode 0=plain, 1=relu(a), 2=LN(g_x)
// grid (n_out/1024, n_in/R), block 256; out += a[i0..i0+R) @ W rows
__global__ void k_gemv4(const float* __restrict__ Wm, const float* __restrict__ a,
                        const float* __restrict__ g, const float* __restrict__ b,
                        float* __restrict__ out, int n_out, int R, int mode,
                        float* z1, int zn1, float* z2, int zn2) {
    __shared__ float sb[32];
    __shared__ float ac[32];
    int tid = threadIdx.x;
    int gt = (blockIdx.y * gridDim.x + blockIdx.x) * 256 + tid;
    int T = gridDim.x * gridDim.y * 256;
    for (int k = gt; k < zn1; k += T) z1[k] = 0.f;
    for (int k = gt; k < zn2; k += T) z2[k] = 0.f;
    int i0 = blockIdx.y * R;
    if (mode == 2) {
        float mean, rstd;
        ln_stats(sb, mean, rstd);
        if (tid < R) { int i = i0 + tid; ac[tid] = (g_x[i] - mean) * rstd * g[i] + b[i]; }
    } else {
        if (tid < R) { float x = a[i0 + tid]; if (mode == 1) x = fmaxf(x, 0.f); ac[tid] = x; }
    }
    __syncthreads();
    int c0 = blockIdx.x * 1024 + tid * 4;
    float4 acc = make_float4(0.f, 0.f, 0.f, 0.f);
#pragma unroll 4
    for (int r = 0; r < R; r++) {
        float4 w = *(const float4*)(Wm + (size_t)(i0 + r) * n_out + c0);
        float ar = ac[r];
        acc.x += ar * w.x; acc.y += ar * w.y; acc.z += ar * w.z; acc.w += ar * w.w;
    }
    float* o = &out[c0];
    atomicAdd(o, acc.x); atomicAdd(o + 1, acc.y);
    atomicAdd(o + 2, acc.z); atomicAdd(o + 3, acc.w);
}

// flash-decode partials: grid (16 heads, 32 chunks), block 128
__global__ void k_attn_part(const float* __restrict__ ck, const float* __restrict__ cv,
                            const int* __restrict__ stepp, int l) {
    __shared__ float4 q4[16];
    __shared__ float sc[64];
    __shared__ float sb[32];
    __shared__ float2 red2[128];
    int tid = threadIdx.x;
    int h = blockIdx.x, c = blockIdx.y;
    int step = stepp[0];
    int n = step + 1;
    int cs = (n + CH - 1) / CH;
    int k0 = c * cs;
    int k1 = min(n, k0 + cs);
    int cnt = k1 - k0;
    if (tid < 16) q4[tid] = ((const float4*)&g_qkv[h * 64])[tid];
    __syncthreads();
    const float* kbase = ck + (size_t)(l * NH + h) * SMAX * DH;
    for (int t = tid; t < cnt; t += 128) {
        int kk = k0 + t;
        const float4* kp = (kk < step) ? (const float4*)(kbase + (size_t)kk * DH)
                                       : (const float4*)(&g_qkv[H + h * 64]);
        float acc = 0.f;
#pragma unroll
        for (int j = 0; j < 16; j++) {
            float4 kv = kp[j];
            float4 q = q4[j];
            acc += kv.x * q.x + kv.y * q.y + kv.z * q.z + kv.w * q.w;
        }
        sc[t] = acc * 0.125f;
    }
    __syncthreads();
    float m = -1e30f;
    for (int i = tid; i < cnt; i += 128) m = fmaxf(m, sc[i]);
    m = br_max(m, sb);
    float s = 0.f;
    for (int i = tid; i < cnt; i += 128) { float e = __expf(sc[i] - m); sc[i] = e; s += e; }
    s = br_sum(s, sb);
    int d2 = tid & 31, part = tid >> 5;
    const float* vbase = cv + (size_t)(l * NH + h) * SMAX * DH;
    float2 acc = make_float2(0.f, 0.f);
    for (int kk = k0 + part; kk < k1; kk += 4) {
        const float2* vp = (kk < step) ? (const float2*)(vbase + (size_t)kk * DH)
                                       : (const float2*)(&g_qkv[2 * H + h * 64]);
        float w = sc[kk - k0];
        float2 v = vp[d2];
        acc.x += w * v.x; acc.y += w * v.y;
    }
    red2[tid] = acc;
    __syncthreads();
    if (part == 0) {
        float2 o;
        o.x = red2[d2].x + red2[32 + d2].x + red2[64 + d2].x + red2[96 + d2].x;
        o.y = red2[d2].y + red2[32 + d2].y + red2[64 + d2].y + red2[96 + d2].y;
        g_po[(h * CH + c) * 64 + 2 * d2]     = o.x;
        g_po[(h * CH + c) * 64 + 2 * d2 + 1] = o.y;
        if (d2 == 0) { g_pm[h * CH + c] = m; g_ps[h * CH + c] = s; }
    }
}

// merge partials -> ao; write k1/v1 into caches; zero g_qc. grid 16, block 128
__global__ void k_attn_merge(float* __restrict__ nk, float* __restrict__ nv,
                             const int* __restrict__ stepp, int l) {
    int h = blockIdx.x, tid = threadIdx.x;
    int step = stepp[0];
    float M = -1e30f;
#pragma unroll
    for (int c = 0; c < CH; c++) M = fmaxf(M, g_pm[h * CH + c]);
    float S = 0.f;
#pragma unroll
    for (int c = 0; c < CH; c++) S += g_ps[h * CH + c] * __expf(g_pm[h * CH + c] - M);
    if (tid < 64) {
        float o = 0.f;
#pragma unroll
        for (int c = 0; c < CH; c++)
            o += __expf(g_pm[h * CH + c] - M) * g_po[(h * CH + c) * 64 + tid];
        g_ao[h * 64 + tid] = o / S;
        g_qc[h * 64 + tid] = 0.f;
    } else {
        int d = tid - 64;
        size_t slot = ((size_t)(l * NH + h) * SMAX + step) * DH + d;
        nk[slot] = g_qkv[H + h * 64 + d];
        nv[slot] = g_qkv[2 * H + h * 64 + d];
    }
}

// U[h][i]: grid 128 blocks x 256 thr; block handles 8 i-rows; float4 loads,
// 16-lane segmented shfl reduce
__global__ void k_U(const float* __restrict__ Ck) {
    __shared__ float4 qs[256];
    int tid = threadIdx.x;
    qs[tid] = ((const float4*)g_qc)[tid];
    __syncthreads();
    float4 q = qs[tid];
    int i0 = blockIdx.x * 8;
    int h = tid >> 4;
#pragma unroll
    for (int r = 0; r < 8; r++) {
        int i = i0 + r;
        float4 w = ((const float4*)(Ck + (size_t)i * H))[tid];
        float v = w.x * q.x + w.y * q.y + w.z * q.z + w.w * q.w;
        v += __shfl_down_sync(0xffffffffu, v, 8);
        v += __shfl_down_sync(0xffffffffu, v, 4);
        v += __shfl_down_sync(0xffffffffu, v, 2);
        v += __shfl_down_sync(0xffffffffu, v, 1);
        if ((tid & 15) == 0) g_U[h * H + i] = v;
    }
}

// scores[h][f]: grid 188, block 512 (warp = head), U register-resident
__global__ void k_scores(const float* __restrict__ enc, const float* __restrict__ cmask) {
    int w = threadIdx.x >> 5, lane = threadIdx.x & 31;
    const float4* up = (const float4*)(g_U + w * H);
    float4 u[8];
#pragma unroll
    for (int j = 0; j < 8; j++) u[j] = up[lane + 32 * j];
#pragma unroll
    for (int ff = 0; ff < 8; ff++) {
        int f = blockIdx.x * 8 + ff;
        if (f >= ENC) break;
        const float4* ep = (const float4*)(enc + (size_t)f * H);
        float acc = 0.f;
#pragma unroll
        for (int j = 0; j < 8; j++) {
            float4 e = ep[lane + 32 * j];
            acc += e.x * u[j].x + e.y * u[j].y + e.z * u[j].z + e.w * u[j].w;
        }
#pragma unroll
        for (int o = 16; o; o >>= 1) acc += __shfl_down_sync(0xffffffffu, acc, o);
        if (lane == 0) g_sc[w * ENC + f] = acc * 0.125f + cmask[f];
    }
}

// per-head softmax; zero g_W, g_outc. grid 16, block 256
__global__ void k_softmax16() {
    __shared__ float sb[32];
    int h = blockIdx.x, tid = threadIdx.x;
    float* row = &g_sc[h * ENC];
    float m = -1e30f;
    for (int i = tid; i < ENC; i += 256) m = fmaxf(m, row[i]);
    m = br_max(m, sb);
    float s = 0.f;
    for (int i = tid; i < ENC; i += 256) { float e = __expf(row[i] - m); row[i] = e; s += e; }
    s = br_sum(s, sb);
    float inv = 1.f / s;
    for (int i = tid; i < ENC; i += 256) row[i] *= inv;
    for (int i = tid; i < H; i += 256) g_W[h * H + i] = 0.f;
    if (h == 0) for (int i = tid; i < H; i += 256) g_outc[i] = 0.f;
}

// W[h][cols] += attc @ enc. grid (4 head-groups, 32 f-chunks), block 256, float4 cols
__global__ void k_wsum(const float* __restrict__ enc) {
    __shared__ float at[4 * FCH];
    int tid = threadIdx.x, fc = blockIdx.y, hg = blockIdx.x;
    for (int idx = tid; idx < 4 * FCH; idx += 256) {
        int hh = idx / FCH, k = idx % FCH;
        int f = fc * FCH + k;
        at[idx] = (f < ENC) ? g_sc[(hg * 4 + hh) * ENC + f] : 0.f;
    }
    __syncthreads();
    int c0 = tid * 4;
    float4 acc[4];
#pragma unroll
    for (int hh = 0; hh < 4; hh++) acc[hh] = make_float4(0.f, 0.f, 0.f, 0.f);
    int fend = min(FCH, ENC - fc * FCH);
    for (int k = 0; k < fend; k++) {
        float4 e = *(const float4*)(enc + (size_t)(fc * FCH + k) * H + c0);
#pragma unroll
        for (int hh = 0; hh < 4; hh++) {
            float a = at[hh * FCH + k];
            acc[hh].x += a * e.x; acc[hh].y += a * e.y;
            acc[hh].z += a * e.z; acc[hh].w += a * e.w;
        }
    }
#pragma unroll
    for (int hh = 0; hh < 4; hh++) {
        float* o = &g_W[(hg * 4 + hh) * H + c0];
        atomicAdd(o, acc[hh].x); atomicAdd(o + 1, acc[hh].y);
        atomicAdd(o + 2, acc[hh].z); atomicAdd(o + 3, acc[hh].w);
    }
}

// outc[col] += sum_i W[h(col),i]*Cv[i,col]; zero g_ffn. grid 128, block 256
__global__ void k_outc(const float* __restrict__ Cv) {
    int tid = threadIdx.x;
    int c0 = tid * 4;
    int h = tid >> 4;
    int i0 = blockIdx.x * 8;
    float4 acc = make_float4(0.f, 0.f, 0.f, 0.f);
#pragma unroll
    for (int r = 0; r < 8; r++) {
        int i = i0 + r;
        float wv = g_W[h * H + i];
        float4 cv4 = *(const float4*)(Cv + (size_t)i * H + c0);
        acc.x += wv * cv4.x; acc.y += wv * cv4.y;
        acc.z += wv * cv4.z; acc.w += wv * cv4.w;
    }
    float* o = &g_outc[c0];
    atomicAdd(o, acc.x); atomicAdd(o + 1, acc.y);
    atomicAdd(o + 2, acc.z); atomicAdd(o + 3, acc.w);
    int gt = blockIdx.x * 256 + tid;
    if (gt < FFN) g_ffn[gt] = 0.f;
}

__global__ void k_logsoftmax(float* __restrict__ out) {
    __shared__ float sb[32];
    int tid = threadIdx.x;
    float m = -1e30f;
    for (int i = tid; i < VOCAB; i += 256) m = fmaxf(m, g_logits[i]);
    m = br_max(m, sb);
    float s = 0.f;
    for (int i = tid; i < VOCAB; i += 256) s += __expf(g_logits[i] - m);
    s = br_sum(s, sb);
    float ls = logf(s);
    for (int i = tid; i < VOCAB; i += 256) out[i] = g_logits[i] - m - ls;
}

// ---------------- host ----------------
extern "C" void kernel_launch(void* const* d_in, const int* in_sizes, int n_in,
                              void* d_out, int out_size) {
    int has_step = (n_in >= 27) ? 1 : 0;
    int idx = 0;
    const int*   input_id = (const int*)d_in[idx++];
    const float* enc      = (const float*)d_in[idx++];
    const float* ck       = (const float*)d_in[idx++];
    const float* cv       = (const float*)d_in[idx++];
    const int*   stepp    = nullptr;
    if (has_step) stepp = (const int*)d_in[idx++];
    const float* cmask = (const float*)d_in[idx++];
    const float* tok   = (const float*)d_in[idx++];
    const float* pos   = (const float*)d_in[idx++];
    const float* Wq = (const float*)d_in[idx++];
    const float* Wk = (const float*)d_in[idx++];
    const float* Wv = (const float*)d_in[idx++];
    const float* Wo = (const float*)d_in[idx++];
    const float* Cq = (const float*)d_in[idx++];
    const float* Ck = (const float*)d_in[idx++];
    const float* Cv = (const float*)d_in[idx++];
    const float* Co = (const float*)d_in[idx++];
    const float* W1 = (const float*)d_in[idx++];
    const float* W2 = (const float*)d_in[idx++];
    const float* ln1g = (const float*)d_in[idx++];
    const float* ln1b = (const float*)d_in[idx++];
    const float* ln2g = (const float*)d_in[idx++];
    const float* ln2b = (const float*)d_in[idx++];
    const float* ln3g = (const float*)d_in[idx++];
    const float* ln3b = (const float*)d_in[idx++];
    const float* lnfg = (const float*)d_in[idx++];
    const float* lnfb = (const float*)d_in[idx++];
    const float* Wout = (const float*)d_in[idx++];

    if (!stepp) {
        void* p;
        cudaGetSymbolAddress(&p, g_step_fallback);
        stepp = (const int*)p;
    }

    float* out = (float*)d_out;
    float* nk = out + VOCAB;
    float* nv = nk + (size_t)L * NH * SMAX * DH;

    float *p_x, *p_ao, *p_qc, *p_outc, *p_ffn, *p_logits, *p_qkv;
    cudaGetSymbolAddress((void**)&p_x, g_x);
    cudaGetSymbolAddress((void**)&p_ao, g_ao);
    cudaGetSymbolAddress((void**)&p_qc, g_qc);
    cudaGetSymbolAddress((void**)&p_outc, g_outc);
    cudaGetSymbolAddress((void**)&p_ffn, g_ffn);
    cudaGetSymbolAddress((void**)&p_logits, g_logits);
    cudaGetSymbolAddress((void**)&p_qkv, g_qkv);

    // one-time side-stream + events (created on the uncaptured correctness call)
    static cudaStream_t s_copy = nullptr;
    static cudaEvent_t ev_fork = nullptr, ev_join = nullptr;
    if (!s_copy) {
        cudaStreamCreateWithFlags(&s_copy, cudaStreamNonBlocking);
        cudaEventCreateWithFlags(&ev_fork, cudaEventDisableTiming);
        cudaEventCreateWithFlags(&ev_join, cudaEventDisableTiming);
    }

    // fork the big cache copy onto the side stream (overlaps the layer chain)
    cudaEventRecord(ev_fork, 0);
    cudaStreamWaitEvent(s_copy, ev_fork, 0);
    k_copy<<<32768, 256, 0, s_copy>>>((const float4*)ck, (const float4*)cv,
                                      (float4*)nk, (float4*)nv, stepp);
    cudaEventRecord(ev_join, s_copy);

    k_init<<<1, 1024>>>(input_id, stepp, tok, pos);

    for (int l = 0; l < L; l++) {
        size_t o = (size_t)l * H * H;
        size_t o1 = (size_t)l * H * FFN;
        size_t o2 = (size_t)l * FFN * H;
        // self-attention
        k_gemv3_ln<<<dim3(3, 64), 256>>>(Wq + o, Wk + o, Wv + o, ln1g + l * H, ln1b + l * H);
        k_attn_part<<<dim3(16, CH), 128>>>(ck, cv, stepp, l);
        k_attn_merge<<<16, 128>>>(nk, nv, stepp, l);
        k_gemv4<<<dim3(1, 128), 256>>>(Wo + o, p_ao, nullptr, nullptr, p_x, H, 8, 0,
                                       nullptr, 0, nullptr, 0);
        // cross-attention (algebraically refactored)
        k_gemv4<<<dim3(1, 128), 256>>>(Cq + o, nullptr, ln2g + l * H, ln2b + l * H, p_qc, H, 8, 2,
                                       nullptr, 0, nullptr, 0);
        k_U<<<128, 256>>>(Ck + o);
        k_scores<<<188, 512>>>(enc, cmask);
        k_softmax16<<<16, 256>>>();
        k_wsum<<<dim3(4, 32), 256>>>(enc);
        k_outc<<<128, 256>>>(Cv + o);
        k_gemv4<<<dim3(1, 128), 256>>>(Co + o, p_outc, nullptr, nullptr, p_x, H, 8, 0,
                                       nullptr, 0, nullptr, 0);
        // FFN
        k_gemv4<<<dim3(4, 64), 256>>>(W1 + o1, nullptr, ln3g + l * H, ln3b + l * H, p_ffn, FFN, 16, 2,
                                      nullptr, 0, nullptr, 0);
        k_gemv4<<<dim3(1, 256), 256>>>(W2 + o2, p_ffn, nullptr, nullptr, p_x, H, 16, 1,
                                       p_qkv, 3 * H, p_logits, VOCAB);
    }
    // final projection + log-softmax
    k_gemv4<<<dim3(8, 64), 256>>>(Wout, nullptr, lnfg, lnfb, p_logits, VOCAB, 16, 2,
                                  nullptr, 0, nullptr, 0);
    k_logsoftmax<<<1, 256>>>(out);

    // join the copy stream back before capture ends
    cudaStreamWaitEvent(0, ev_join, 0);
}